// round 4
// baseline (speedup 1.0000x reference)
#include <cuda_runtime.h>
#include <cstdint>

// Problem constants
#define B_    32
#define H_    14
#define W_    14
#define L_    196          // H*W
#define NPOS  6272         // B*L
#define CIN   1024
#define WIDTH 256
#define OUTC  1024
#define KC    16           // codewords per codebook
#define TILE_N 32          // positions per block

// ---------------- scratch (static device allocations only) ----------------
__device__ float g_out1[WIDTH * NPOS];   // channel-major [c][n]
__device__ float g_out2[WIDTH * NPOS];
__device__ float g_out3[OUTC  * NPOS];
__device__ float g_sc1[WIDTH], g_sh1[WIDTH];
__device__ float g_sc2[WIDTH], g_sh2[WIDTH];
__device__ float g_sc3[OUTC],  g_sh3[OUTC];

// ---------------- packed f32x2 helpers (FFMA2: 2 FMAs per issue) ----------
__device__ __forceinline__ void fma2(unsigned long long& d,
                                     unsigned long long a, unsigned long long b) {
    asm("fma.rn.f32x2 %0, %1, %2, %0;" : "+l"(d) : "l"(a), "l"(b));
}
__device__ __forceinline__ unsigned long long pack2(float lo, float hi) {
    unsigned long long r;
    asm("mov.b64 %0, {%1, %2};" : "=l"(r) : "f"(lo), "f"(hi));
    return r;
}
__device__ __forceinline__ float2 unpack2(unsigned long long v) {
    float2 r;
    asm("mov.b64 {%0, %1}, %2;" : "=f"(r.x), "=f"(r.y) : "l"(v));
    return r;
}

// GEMM inner tile: 8 positions x 4 columns per thread, f32x2 packed.
// attn2: [32][18] ull, {a,a} duplicated pairs. lut_s: float[16][256].
#define GEMM_CORE(attn2_s, lut_s, pn, po, acc01, acc23)                         \
    _Pragma("unroll")                                                           \
    for (int kh = 0; kh < 8; ++kh) {                                            \
        const ulonglong2 bv0 = ((const ulonglong2*)(lut_s))[(2*kh)   * 64 + po];\
        const ulonglong2 bv1 = ((const ulonglong2*)(lut_s))[(2*kh+1) * 64 + po];\
        _Pragma("unroll")                                                       \
        for (int i = 0; i < 8; ++i) {                                           \
            const ulonglong2 av =                                               \
                ((const ulonglong2*)((attn2_s) + ((pn)*8 + i) * 18))[kh];       \
            fma2(acc01[i], av.x, bv0.x);                                        \
            fma2(acc23[i], av.x, bv0.y);                                        \
            fma2(acc01[i], av.y, bv1.x);                                        \
            fma2(acc23[i], av.y, bv1.y);                                        \
        }                                                                       \
    }

// ======================= AMM layer 1 (1x1, ncb=256, sub=4) =================
__global__ __launch_bounds__(256, 2) void amm1_kernel(
    const float* __restrict__ x, const float* __restrict__ cent,
    const float* __restrict__ lut, const float* __restrict__ invt_p)
{
    __shared__ float lut_s[KC * WIDTH];                 // 16 KB
    __shared__ unsigned long long attn2_s[TILE_N * 18]; // {a,a} pairs, 4.5 KB
    __shared__ float xv_s[4 * TILE_N];

    const int t  = threadIdx.x;
    const int n0 = blockIdx.x * TILE_N;
    const float invt = __ldg(invt_p);

    const int po = t & 63;     // column group: cols po*4 .. po*4+3
    const int pn = t >> 6;     // position group: pos pn*8 .. pn*8+7
    unsigned long long acc01[8], acc23[8];
#pragma unroll
    for (int i = 0; i < 8; ++i) { acc01[i] = 0ull; acc23[i] = 0ull; }

    // xv loader mapping (threads 0..127)
    const int lj  = t >> 5;
    const int lnl = t & 31;
    const int ln  = n0 + lnl;
    const int lb  = ln / L_;
    const int ll  = ln - lb * L_;
    const float* xbase = x + (size_t)lb * CIN * L_ + ll;

    // scoring mapping: warp sw, 16-lane group grp, codeword kk
    const int sw   = t >> 5;
    const int lane = t & 31;
    const int grp  = lane >> 4;
    const int kk   = lane & 15;

    for (int c = 0; c < 256; ++c) {
        // prefetch LUT slice into registers (latency hidden behind scoring)
        float4 lr[4];
        const float4* lp = (const float4*)(lut + (size_t)c * KC * WIDTH);
#pragma unroll
        for (int i = 0; i < 4; ++i) lr[i] = __ldg(lp + t + i * 256);

        if (lj < 4)
            xv_s[lj * TILE_N + lnl] = __ldg(xbase + (c * 4 + lj) * L_);
        __syncthreads();

        // scoring + softmax (each 16-lane group handles one position per pass)
        {
            const float* cp = cent + (size_t)(c * KC + kk) * 4;
            const float c0 = __ldg(cp + 0), c1 = __ldg(cp + 1);
            const float c2 = __ldg(cp + 2), c3 = __ldg(cp + 3);
            const float nrm = c0 * c0 + c1 * c1 + c2 * c2 + c3 * c3;
#pragma unroll
            for (int pass = 0; pass < 2; ++pass) {
                const int nl = pass * 16 + sw * 2 + grp;
                float s = c0 * xv_s[0 * TILE_N + nl] + c1 * xv_s[1 * TILE_N + nl]
                        + c2 * xv_s[2 * TILE_N + nl] + c3 * xv_s[3 * TILE_N + nl];
                s = (2.f * s - nrm) * invt;
                float m = s;
#pragma unroll
                for (int d = 8; d; d >>= 1)
                    m = fmaxf(m, __shfl_xor_sync(0xffffffffu, m, d, 16));
                const float e = __expf(s - m);
                float sum = e;
#pragma unroll
                for (int d = 8; d; d >>= 1)
                    sum += __shfl_xor_sync(0xffffffffu, sum, d, 16);
                const float p = e / sum;
                attn2_s[nl * 18 + kk] = pack2(p, p);
            }
        }
#pragma unroll
        for (int i = 0; i < 4; ++i) ((float4*)lut_s)[t + i * 256] = lr[i];
        __syncthreads();

        GEMM_CORE(attn2_s, lut_s, pn, po, acc01, acc23)
        __syncthreads();
    }

    // store channel-major
#pragma unroll
    for (int i = 0; i < 8; ++i) {
        const float2 v01 = unpack2(acc01[i]);
        const float2 v23 = unpack2(acc23[i]);
        const int n = n0 + pn * 8 + i;
        g_out1[(size_t)(po * 4 + 0) * NPOS + n] = v01.x;
        g_out1[(size_t)(po * 4 + 1) * NPOS + n] = v01.y;
        g_out1[(size_t)(po * 4 + 2) * NPOS + n] = v23.x;
        g_out1[(size_t)(po * 4 + 3) * NPOS + n] = v23.y;
    }
}

// ============ AMM layer 2 (3x3 patches, ncb=256, sub=9, bn1+relu fused) ====
__global__ __launch_bounds__(256, 2) void amm2_kernel(
    const float* __restrict__ cent, const float* __restrict__ lut,
    const float* __restrict__ invt_p)
{
    __shared__ float lut_s[KC * WIDTH];
    __shared__ unsigned long long attn2_s[TILE_N * 18];
    __shared__ float xv_s[9 * TILE_N];

    const int t  = threadIdx.x;
    const int n0 = blockIdx.x * TILE_N;
    const float invt = __ldg(invt_p);

    const int po = t & 63;
    const int pn = t >> 6;
    unsigned long long acc01[8], acc23[8];
#pragma unroll
    for (int i = 0; i < 8; ++i) { acc01[i] = 0ull; acc23[i] = 0ull; }

    // precompute patch-gather slots (288 entries over 256 threads -> 2 rounds)
    int posn[2]; bool vld[2];
#pragma unroll
    for (int r = 0; r < 2; ++r) {
        const int idx = t + r * 256;
        vld[r] = false; posn[r] = 0;
        if (idx < 9 * TILE_N) {
            const int s9 = idx >> 5, nl = idx & 31;
            const int n = n0 + nl;
            const int b = n / L_;
            const int l = n - b * L_;
            const int h = l / W_, w = l - (l / W_) * W_;
            const int hh = h + s9 / 3 - 1;
            const int ww = w + s9 % 3 - 1;
            if (hh >= 0 && hh < H_ && ww >= 0 && ww < W_) {
                vld[r]  = true;
                posn[r] = b * L_ + hh * W_ + ww;
            }
        }
    }

    const int sw = t >> 5, lane = t & 31, grp = lane >> 4, kk = lane & 15;

    for (int c = 0; c < 256; ++c) {
        float4 lr[4];
        const float4* lp = (const float4*)(lut + (size_t)c * KC * WIDTH);
#pragma unroll
        for (int i = 0; i < 4; ++i) lr[i] = __ldg(lp + t + i * 256);

        const float sc1 = g_sc1[c], sh1 = g_sh1[c];
#pragma unroll
        for (int r = 0; r < 2; ++r) {
            const int idx = t + r * 256;
            if (idx < 9 * TILE_N) {
                float v = 0.f;
                if (vld[r])
                    v = fmaxf(g_out1[(size_t)c * NPOS + posn[r]] * sc1 + sh1, 0.f);
                xv_s[idx] = v;
            }
        }
        __syncthreads();

        {
            const float* cp = cent + (size_t)(c * KC + kk) * 9;
            float cw[9]; float nrm = 0.f;
#pragma unroll
            for (int j = 0; j < 9; ++j) { cw[j] = __ldg(cp + j); nrm += cw[j] * cw[j]; }
#pragma unroll
            for (int pass = 0; pass < 2; ++pass) {
                const int nl = pass * 16 + sw * 2 + grp;
                float s = 0.f;
#pragma unroll
                for (int j = 0; j < 9; ++j) s += cw[j] * xv_s[j * TILE_N + nl];
                s = (2.f * s - nrm) * invt;
                float m = s;
#pragma unroll
                for (int d = 8; d; d >>= 1)
                    m = fmaxf(m, __shfl_xor_sync(0xffffffffu, m, d, 16));
                const float e = __expf(s - m);
                float sum = e;
#pragma unroll
                for (int d = 8; d; d >>= 1)
                    sum += __shfl_xor_sync(0xffffffffu, sum, d, 16);
                const float p = e / sum;
                attn2_s[nl * 18 + kk] = pack2(p, p);
            }
        }
#pragma unroll
        for (int i = 0; i < 4; ++i) ((float4*)lut_s)[t + i * 256] = lr[i];
        __syncthreads();

        GEMM_CORE(attn2_s, lut_s, pn, po, acc01, acc23)
        __syncthreads();
    }

#pragma unroll
    for (int i = 0; i < 8; ++i) {
        const float2 v01 = unpack2(acc01[i]);
        const float2 v23 = unpack2(acc23[i]);
        const int n = n0 + pn * 8 + i;
        g_out2[(size_t)(po * 4 + 0) * NPOS + n] = v01.x;
        g_out2[(size_t)(po * 4 + 1) * NPOS + n] = v01.y;
        g_out2[(size_t)(po * 4 + 2) * NPOS + n] = v23.x;
        g_out2[(size_t)(po * 4 + 3) * NPOS + n] = v23.y;
    }
}

// ======= AMM layer 3 (1x1, ncb=64, sub=4, out=1024, bn2+relu fused) ========
// grid.y splits the 1024 output columns into 4 chunks of 256
__global__ __launch_bounds__(256, 2) void amm3_kernel(
    const float* __restrict__ cent, const float* __restrict__ lut,
    const float* __restrict__ invt_p)
{
    __shared__ float lut_s[KC * WIDTH];
    __shared__ unsigned long long attn2_s[TILE_N * 18];
    __shared__ float xv_s[4 * TILE_N];

    const int t  = threadIdx.x;
    const int n0 = blockIdx.x * TILE_N;
    const int obase = blockIdx.y << 8;
    const float invt = __ldg(invt_p);

    const int po = t & 63;
    const int pn = t >> 6;
    unsigned long long acc01[8], acc23[8];
#pragma unroll
    for (int i = 0; i < 8; ++i) { acc01[i] = 0ull; acc23[i] = 0ull; }

    const int lj  = t >> 5;
    const int lnl = t & 31;
    const int ln  = n0 + lnl;

    const int k0 = t >> 6;   // lut-row base for staging
    const int o4 = t & 63;   // float4 column within row

    const int sw = t >> 5, lane = t & 31, grp = lane >> 4, kk = lane & 15;

    for (int c = 0; c < 64; ++c) {
        float4 lr[4];
#pragma unroll
        for (int i = 0; i < 4; ++i)
            lr[i] = __ldg((const float4*)(lut + (size_t)(c * KC + k0 + i * 4) * OUTC + obase) + o4);

        if (lj < 4) {
            const int ch = c * 4 + lj;
            const float v = g_out2[(size_t)ch * NPOS + ln] * g_sc2[ch] + g_sh2[ch];
            xv_s[lj * TILE_N + lnl] = fmaxf(v, 0.f);
        }
        __syncthreads();

        {
            const float* cp = cent + (size_t)(c * KC + kk) * 4;
            const float c0 = __ldg(cp + 0), c1 = __ldg(cp + 1);
            const float c2 = __ldg(cp + 2), c3 = __ldg(cp + 3);
            const float nrm = c0 * c0 + c1 * c1 + c2 * c2 + c3 * c3;
#pragma unroll
            for (int pass = 0; pass < 2; ++pass) {
                const int nl = pass * 16 + sw * 2 + grp;
                float s = c0 * xv_s[0 * TILE_N + nl] + c1 * xv_s[1 * TILE_N + nl]
                        + c2 * xv_s[2 * TILE_N + nl] + c3 * xv_s[3 * TILE_N + nl];
                s = (2.f * s - nrm) * invt;
                float m = s;
#pragma unroll
                for (int d = 8; d; d >>= 1)
                    m = fmaxf(m, __shfl_xor_sync(0xffffffffu, m, d, 16));
                const float e = __expf(s - m);
                float sum = e;
#pragma unroll
                for (int d = 8; d; d >>= 1)
                    sum += __shfl_xor_sync(0xffffffffu, sum, d, 16);
                const float p = e / sum;
                attn2_s[nl * 18 + kk] = pack2(p, p);
            }
        }
#pragma unroll
        for (int i = 0; i < 4; ++i) ((float4*)lut_s)[t + i * 256] = lr[i];
        __syncthreads();

        GEMM_CORE(attn2_s, lut_s, pn, po, acc01, acc23)
        __syncthreads();
    }

#pragma unroll
    for (int i = 0; i < 8; ++i) {
        const float2 v01 = unpack2(acc01[i]);
        const float2 v23 = unpack2(acc23[i]);
        const int n = n0 + pn * 8 + i;
        const int o = obase + po * 4;
        g_out3[(size_t)(o + 0) * NPOS + n] = v01.x;
        g_out3[(size_t)(o + 1) * NPOS + n] = v01.y;
        g_out3[(size_t)(o + 2) * NPOS + n] = v23.x;
        g_out3[(size_t)(o + 3) * NPOS + n] = v23.y;
    }
}

// ================== BN batch-stats (one block per channel) =================
__global__ __launch_bounds__(256) void bn_stats_kernel(
    int which, const float* __restrict__ gw, const float* __restrict__ bw)
{
    const float* data; float* scale; float* shift;
    if (which == 0)      { data = g_out1; scale = g_sc1; shift = g_sh1; }
    else if (which == 1) { data = g_out2; scale = g_sc2; shift = g_sh2; }
    else                 { data = g_out3; scale = g_sc3; shift = g_sh3; }

    const int c = blockIdx.x, t = threadIdx.x;
    const float* p = data + (size_t)c * NPOS;
    float s = 0.f, s2 = 0.f;
    for (int i = t; i < NPOS; i += 256) {
        const float v = p[i];
        s += v; s2 += v * v;
    }
#pragma unroll
    for (int d = 16; d; d >>= 1) {
        s  += __shfl_xor_sync(0xffffffffu, s,  d);
        s2 += __shfl_xor_sync(0xffffffffu, s2, d);
    }
    __shared__ float sh_s[8], sh_s2[8];
    if ((t & 31) == 0) { sh_s[t >> 5] = s; sh_s2[t >> 5] = s2; }
    __syncthreads();
    if (t == 0) {
        s = 0.f; s2 = 0.f;
#pragma unroll
        for (int i = 0; i < 8; ++i) { s += sh_s[i]; s2 += sh_s2[i]; }
        const float m   = s  * (1.f / NPOS);
        const float var = s2 * (1.f / NPOS) - m * m;
        const float sc  = __ldg(gw + c) * rsqrtf(var + 1e-5f);
        scale[c] = sc;
        shift[c] = __ldg(bw + c) - m * sc;
    }
}

// ============== final: bn3 + residual + relu, channel-major out ============
__global__ __launch_bounds__(256) void final_kernel(
    const float* __restrict__ x, float* __restrict__ out)
{
    const int idx = blockIdx.x * 256 + threadIdx.x;
    if (idx >= B_ * OUTC * L_) return;
    const int l = idx % L_;
    const int c = (idx / L_) % OUTC;
    const int b = idx / (L_ * OUTC);
    const int n = b * L_ + l;
    const float v = g_out3[(size_t)c * NPOS + n] * g_sc3[c] + g_sh3[c] + x[idx];
    out[idx] = fmaxf(v, 0.f);
}

// ==========================================================================
extern "C" void kernel_launch(void* const* d_in, const int* in_sizes, int n_in,
                              void* d_out, int out_size)
{
    (void)in_sizes; (void)n_in; (void)out_size;
    const float* x    = (const float*)d_in[0];
    const float* c1c  = (const float*)d_in[1];
    const float* c1l  = (const float*)d_in[2];
    const float* c1t  = (const float*)d_in[3];
    const float* c2c  = (const float*)d_in[4];
    const float* c2l  = (const float*)d_in[5];
    const float* c2t  = (const float*)d_in[6];
    const float* c3c  = (const float*)d_in[7];
    const float* c3l  = (const float*)d_in[8];
    const float* c3t  = (const float*)d_in[9];
    const float* bn1g = (const float*)d_in[10];
    const float* bn1b = (const float*)d_in[11];
    const float* bn2g = (const float*)d_in[12];
    const float* bn2b = (const float*)d_in[13];
    const float* bn3g = (const float*)d_in[14];
    const float* bn3b = (const float*)d_in[15];
    float* out = (float*)d_out;

    amm1_kernel<<<NPOS / TILE_N, 256>>>(x, c1c, c1l, c1t);
    bn_stats_kernel<<<WIDTH, 256>>>(0, bn1g, bn1b);
    amm2_kernel<<<NPOS / TILE_N, 256>>>(c2c, c2l, c2t);
    bn_stats_kernel<<<WIDTH, 256>>>(1, bn2g, bn2b);
    amm3_kernel<<<dim3(NPOS / TILE_N, 4), 256>>>(c3c, c3l, c3t);
    bn_stats_kernel<<<OUTC, 256>>>(2, bn3g, bn3b);
    final_kernel<<<(B_ * OUTC * L_ + 255) / 256, 256>>>(x, out);
}

// round 6
// speedup vs baseline: 1.6349x; 1.6349x over previous
#include <cuda_runtime.h>
#include <cstdint>

// Problem constants
#define B_    32
#define H_    14
#define W_    14
#define L_    196          // H*W
#define NPOS  6272         // B*L
#define CIN   1024
#define WIDTH 256
#define OUTC  1024
#define KC    16           // codewords per codebook
#define TILE_N 32          // positions per block

// ---------------- scratch (static device allocations only) ----------------
__device__ float g_out1[WIDTH * NPOS];   // channel-major [c][n]
__device__ float g_out2[WIDTH * NPOS];
__device__ float g_out3[OUTC  * NPOS];
__device__ float g_sc1[WIDTH], g_sh1[WIDTH];
__device__ float g_sc2[WIDTH], g_sh2[WIDTH];
__device__ float g_sc3[OUTC],  g_sh3[OUTC];

// ---------------- packed f32x2 helpers (FFMA2: 2 FMAs per issue) ----------
__device__ __forceinline__ void fma2(unsigned long long& d,
                                     unsigned long long a, unsigned long long b) {
    asm("fma.rn.f32x2 %0, %1, %2, %0;" : "+l"(d) : "l"(a), "l"(b));
}
__device__ __forceinline__ unsigned long long pack2(float lo, float hi) {
    unsigned long long r;
    asm("mov.b64 %0, {%1, %2};" : "=l"(r) : "f"(lo), "f"(hi));
    return r;
}
__device__ __forceinline__ float2 unpack2(unsigned long long v) {
    float2 r;
    asm("mov.b64 {%0, %1}, %2;" : "=f"(r.x), "=f"(r.y) : "l"(v));
    return r;
}

// GEMM inner tile: 8 positions x 4 columns per thread, f32x2 packed.
// attn2: [32][18] ull, {a,a} duplicated pairs. lut_s: float[16][256].
#define GEMM_CORE(attn2_s, lut_s, pn, po, acc01, acc23)                         \
    _Pragma("unroll")                                                           \
    for (int kh = 0; kh < 8; ++kh) {                                            \
        const ulonglong2 bv0 = ((const ulonglong2*)(lut_s))[(2*kh)   * 64 + po];\
        const ulonglong2 bv1 = ((const ulonglong2*)(lut_s))[(2*kh+1) * 64 + po];\
        _Pragma("unroll")                                                       \
        for (int i = 0; i < 8; ++i) {                                           \
            const ulonglong2 av =                                               \
                ((const ulonglong2*)((attn2_s) + ((pn)*8 + i) * 18))[kh];       \
            fma2(acc01[i], av.x, bv0.x);                                        \
            fma2(acc23[i], av.x, bv0.y);                                        \
            fma2(acc01[i], av.y, bv1.x);                                        \
            fma2(acc23[i], av.y, bv1.y);                                        \
        }                                                                       \
    }

// ======================= AMM layer 1 (1x1, ncb=256, sub=4) =================
__global__ __launch_bounds__(256, 2) void amm1_kernel(
    const float* __restrict__ x, const float* __restrict__ cent,
    const float* __restrict__ lut, const float* __restrict__ invt_p)
{
    __shared__ float lut_s[KC * WIDTH];                 // 16 KB
    __shared__ unsigned long long attn2_s[TILE_N * 18]; // {a,a} pairs, 4.5 KB
    __shared__ float xv_s[4 * TILE_N];

    const int t  = threadIdx.x;
    const int n0 = blockIdx.x * TILE_N;
    const float invt = __ldg(invt_p);

    const int po = t & 63;     // column group: cols po*4 .. po*4+3
    const int pn = t >> 6;     // position group: pos pn*8 .. pn*8+7
    unsigned long long acc01[8], acc23[8];
#pragma unroll
    for (int i = 0; i < 8; ++i) { acc01[i] = 0ull; acc23[i] = 0ull; }

    // xv loader mapping (threads 0..127)
    const int lj  = t >> 5;
    const int lnl = t & 31;
    const int ln  = n0 + lnl;
    const int lb  = ln / L_;
    const int ll  = ln - lb * L_;
    const float* xbase = x + (size_t)lb * CIN * L_ + ll;

    // scoring mapping: warp sw, 16-lane group grp, codeword kk
    const int sw   = t >> 5;
    const int lane = t & 31;
    const int grp  = lane >> 4;
    const int kk   = lane & 15;

    for (int c = 0; c < 256; ++c) {
        // prefetch LUT slice into registers (latency hidden behind scoring)
        float4 lr[4];
        const float4* lp = (const float4*)(lut + (size_t)c * KC * WIDTH);
#pragma unroll
        for (int i = 0; i < 4; ++i) lr[i] = __ldg(lp + t + i * 256);

        if (lj < 4)
            xv_s[lj * TILE_N + lnl] = __ldg(xbase + (c * 4 + lj) * L_);
        __syncthreads();

        // scoring + softmax (each 16-lane group handles one position per pass)
        {
            const float* cp = cent + (size_t)(c * KC + kk) * 4;
            const float c0 = __ldg(cp + 0), c1 = __ldg(cp + 1);
            const float c2 = __ldg(cp + 2), c3 = __ldg(cp + 3);
            const float nrm = c0 * c0 + c1 * c1 + c2 * c2 + c3 * c3;
#pragma unroll
            for (int pass = 0; pass < 2; ++pass) {
                const int nl = pass * 16 + sw * 2 + grp;
                float s = c0 * xv_s[0 * TILE_N + nl] + c1 * xv_s[1 * TILE_N + nl]
                        + c2 * xv_s[2 * TILE_N + nl] + c3 * xv_s[3 * TILE_N + nl];
                s = (2.f * s - nrm) * invt;
                float m = s;
#pragma unroll
                for (int d = 8; d; d >>= 1)
                    m = fmaxf(m, __shfl_xor_sync(0xffffffffu, m, d, 16));
                const float e = __expf(s - m);
                float sum = e;
#pragma unroll
                for (int d = 8; d; d >>= 1)
                    sum += __shfl_xor_sync(0xffffffffu, sum, d, 16);
                const float p = e / sum;
                attn2_s[nl * 18 + kk] = pack2(p, p);
            }
        }
#pragma unroll
        for (int i = 0; i < 4; ++i) ((float4*)lut_s)[t + i * 256] = lr[i];
        __syncthreads();

        GEMM_CORE(attn2_s, lut_s, pn, po, acc01, acc23)
        __syncthreads();
    }

    // store channel-major
#pragma unroll
    for (int i = 0; i < 8; ++i) {
        const float2 v01 = unpack2(acc01[i]);
        const float2 v23 = unpack2(acc23[i]);
        const int n = n0 + pn * 8 + i;
        g_out1[(size_t)(po * 4 + 0) * NPOS + n] = v01.x;
        g_out1[(size_t)(po * 4 + 1) * NPOS + n] = v01.y;
        g_out1[(size_t)(po * 4 + 2) * NPOS + n] = v23.x;
        g_out1[(size_t)(po * 4 + 3) * NPOS + n] = v23.y;
    }
}

// ============ AMM layer 2 (3x3 patches, ncb=256, sub=9, bn1+relu fused) ====
__global__ __launch_bounds__(256, 2) void amm2_kernel(
    const float* __restrict__ cent, const float* __restrict__ lut,
    const float* __restrict__ invt_p)
{
    __shared__ float lut_s[KC * WIDTH];
    __shared__ unsigned long long attn2_s[TILE_N * 18];
    __shared__ float xv_s[9 * TILE_N];

    const int t  = threadIdx.x;
    const int n0 = blockIdx.x * TILE_N;
    const float invt = __ldg(invt_p);

    const int po = t & 63;
    const int pn = t >> 6;
    unsigned long long acc01[8], acc23[8];
#pragma unroll
    for (int i = 0; i < 8; ++i) { acc01[i] = 0ull; acc23[i] = 0ull; }

    // precompute patch-gather slots (288 entries over 256 threads -> 2 rounds)
    int posn[2]; bool vld[2];
#pragma unroll
    for (int r = 0; r < 2; ++r) {
        const int idx = t + r * 256;
        vld[r] = false; posn[r] = 0;
        if (idx < 9 * TILE_N) {
            const int s9 = idx >> 5, nl = idx & 31;
            const int n = n0 + nl;
            const int b = n / L_;
            const int l = n - b * L_;
            const int h = l / W_, w = l - (l / W_) * W_;
            const int hh = h + s9 / 3 - 1;
            const int ww = w + s9 % 3 - 1;
            if (hh >= 0 && hh < H_ && ww >= 0 && ww < W_) {
                vld[r]  = true;
                posn[r] = b * L_ + hh * W_ + ww;
            }
        }
    }

    const int sw = t >> 5, lane = t & 31, grp = lane >> 4, kk = lane & 15;

    for (int c = 0; c < 256; ++c) {
        float4 lr[4];
        const float4* lp = (const float4*)(lut + (size_t)c * KC * WIDTH);
#pragma unroll
        for (int i = 0; i < 4; ++i) lr[i] = __ldg(lp + t + i * 256);

        const float sc1 = g_sc1[c], sh1 = g_sh1[c];
#pragma unroll
        for (int r = 0; r < 2; ++r) {
            const int idx = t + r * 256;
            if (idx < 9 * TILE_N) {
                float v = 0.f;
                if (vld[r])
                    v = fmaxf(g_out1[(size_t)c * NPOS + posn[r]] * sc1 + sh1, 0.f);
                xv_s[idx] = v;
            }
        }
        __syncthreads();

        {
            const float* cp = cent + (size_t)(c * KC + kk) * 9;
            float cw[9]; float nrm = 0.f;
#pragma unroll
            for (int j = 0; j < 9; ++j) { cw[j] = __ldg(cp + j); nrm += cw[j] * cw[j]; }
#pragma unroll
            for (int pass = 0; pass < 2; ++pass) {
                const int nl = pass * 16 + sw * 2 + grp;
                float s = 0.f;
#pragma unroll
                for (int j = 0; j < 9; ++j) s += cw[j] * xv_s[j * TILE_N + nl];
                s = (2.f * s - nrm) * invt;
                float m = s;
#pragma unroll
                for (int d = 8; d; d >>= 1)
                    m = fmaxf(m, __shfl_xor_sync(0xffffffffu, m, d, 16));
                const float e = __expf(s - m);
                float sum = e;
#pragma unroll
                for (int d = 8; d; d >>= 1)
                    sum += __shfl_xor_sync(0xffffffffu, sum, d, 16);
                const float p = e / sum;
                attn2_s[nl * 18 + kk] = pack2(p, p);
            }
        }
#pragma unroll
        for (int i = 0; i < 4; ++i) ((float4*)lut_s)[t + i * 256] = lr[i];
        __syncthreads();

        GEMM_CORE(attn2_s, lut_s, pn, po, acc01, acc23)
        __syncthreads();
    }

#pragma unroll
    for (int i = 0; i < 8; ++i) {
        const float2 v01 = unpack2(acc01[i]);
        const float2 v23 = unpack2(acc23[i]);
        const int n = n0 + pn * 8 + i;
        g_out2[(size_t)(po * 4 + 0) * NPOS + n] = v01.x;
        g_out2[(size_t)(po * 4 + 1) * NPOS + n] = v01.y;
        g_out2[(size_t)(po * 4 + 2) * NPOS + n] = v23.x;
        g_out2[(size_t)(po * 4 + 3) * NPOS + n] = v23.y;
    }
}

// ======= AMM layer 3 (1x1, ncb=64, sub=4, out=1024, bn2+relu fused) ========
// grid.y splits the 1024 output columns into 4 chunks of 256
__global__ __launch_bounds__(256, 2) void amm3_kernel(
    const float* __restrict__ cent, const float* __restrict__ lut,
    const float* __restrict__ invt_p)
{
    __shared__ float lut_s[KC * WIDTH];
    __shared__ unsigned long long attn2_s[TILE_N * 18];
    __shared__ float xv_s[4 * TILE_N];

    const int t  = threadIdx.x;
    const int n0 = blockIdx.x * TILE_N;
    const int obase = blockIdx.y << 8;
    const float invt = __ldg(invt_p);

    const int po = t & 63;
    const int pn = t >> 6;
    unsigned long long acc01[8], acc23[8];
#pragma unroll
    for (int i = 0; i < 8; ++i) { acc01[i] = 0ull; acc23[i] = 0ull; }

    const int lj  = t >> 5;
    const int lnl = t & 31;
    const int ln  = n0 + lnl;

    const int k0 = t >> 6;   // lut-row base for staging
    const int o4 = t & 63;   // float4 column within row

    const int sw = t >> 5, lane = t & 31, grp = lane >> 4, kk = lane & 15;

    for (int c = 0; c < 64; ++c) {
        float4 lr[4];
#pragma unroll
        for (int i = 0; i < 4; ++i)
            lr[i] = __ldg((const float4*)(lut + (size_t)(c * KC + k0 + i * 4) * OUTC + obase) + o4);

        if (lj < 4) {
            const int ch = c * 4 + lj;
            const float v = g_out2[(size_t)ch * NPOS + ln] * g_sc2[ch] + g_sh2[ch];
            xv_s[lj * TILE_N + lnl] = fmaxf(v, 0.f);
        }
        __syncthreads();

        {
            const float* cp = cent + (size_t)(c * KC + kk) * 4;
            const float c0 = __ldg(cp + 0), c1 = __ldg(cp + 1);
            const float c2 = __ldg(cp + 2), c3 = __ldg(cp + 3);
            const float nrm = c0 * c0 + c1 * c1 + c2 * c2 + c3 * c3;
#pragma unroll
            for (int pass = 0; pass < 2; ++pass) {
                const int nl = pass * 16 + sw * 2 + grp;
                float s = c0 * xv_s[0 * TILE_N + nl] + c1 * xv_s[1 * TILE_N + nl]
                        + c2 * xv_s[2 * TILE_N + nl] + c3 * xv_s[3 * TILE_N + nl];
                s = (2.f * s - nrm) * invt;
                float m = s;
#pragma unroll
                for (int d = 8; d; d >>= 1)
                    m = fmaxf(m, __shfl_xor_sync(0xffffffffu, m, d, 16));
                const float e = __expf(s - m);
                float sum = e;
#pragma unroll
                for (int d = 8; d; d >>= 1)
                    sum += __shfl_xor_sync(0xffffffffu, sum, d, 16);
                const float p = e / sum;
                attn2_s[nl * 18 + kk] = pack2(p, p);
            }
        }
#pragma unroll
        for (int i = 0; i < 4; ++i) ((float4*)lut_s)[t + i * 256] = lr[i];
        __syncthreads();

        GEMM_CORE(attn2_s, lut_s, pn, po, acc01, acc23)
        __syncthreads();
    }

#pragma unroll
    for (int i = 0; i < 8; ++i) {
        const float2 v01 = unpack2(acc01[i]);
        const float2 v23 = unpack2(acc23[i]);
        const int n = n0 + pn * 8 + i;
        const int o = obase + po * 4;
        g_out3[(size_t)(o + 0) * NPOS + n] = v01.x;
        g_out3[(size_t)(o + 1) * NPOS + n] = v01.y;
        g_out3[(size_t)(o + 2) * NPOS + n] = v23.x;
        g_out3[(size_t)(o + 3) * NPOS + n] = v23.y;
    }
}

// ================== BN batch-stats (one block per channel) =================
__global__ __launch_bounds__(256) void bn_stats_kernel(
    int which, const float* __restrict__ gw, const float* __restrict__ bw)
{
    const float* data; float* scale; float* shift;
    if (which == 0)      { data = g_out1; scale = g_sc1; shift = g_sh1; }
    else if (which == 1) { data = g_out2; scale = g_sc2; shift = g_sh2; }
    else                 { data = g_out3; scale = g_sc3; shift = g_sh3; }

    const int c = blockIdx.x, t = threadIdx.x;
    const float* p = data + (size_t)c * NPOS;
    float s = 0.f, s2 = 0.f;
    for (int i = t; i < NPOS; i += 256) {
        const float v = p[i];
        s += v; s2 += v * v;
    }
#pragma unroll
    for (int d = 16; d; d >>= 1) {
        s  += __shfl_xor_sync(0xffffffffu, s,  d);
        s2 += __shfl_xor_sync(0xffffffffu, s2, d);
    }
    __shared__ float sh_s[8], sh_s2[8];
    if ((t & 31) == 0) { sh_s[t >> 5] = s; sh_s2[t >> 5] = s2; }
    __syncthreads();
    if (t == 0) {
        s = 0.f; s2 = 0.f;
#pragma unroll
        for (int i = 0; i < 8; ++i) { s += sh_s[i]; s2 += sh_s2[i]; }
        const float m   = s  * (1.f / NPOS);
        const float var = s2 * (1.f / NPOS) - m * m;
        const float sc  = __ldg(gw + c) * rsqrtf(var + 1e-5f);
        scale[c] = sc;
        shift[c] = __ldg(bw + c) - m * sc;
    }
}

// ============== final: bn3 + residual + relu, channel-major out ============
__global__ __launch_bounds__(256) void final_kernel(
    const float* __restrict__ x, float* __restrict__ out)
{
    const int idx = blockIdx.x * 256 + threadIdx.x;
    if (idx >= B_ * OUTC * L_) return;
    const int l = idx % L_;
    const int c = (idx / L_) % OUTC;
    const int b = idx / (L_ * OUTC);
    const int n = b * L_ + l;
    const float v = g_out3[(size_t)c * NPOS + n] * g_sc3[c] + g_sh3[c] + x[idx];
    out[idx] = fmaxf(v, 0.f);
}

// ==========================================================================
extern "C" void kernel_launch(void* const* d_in, const int* in_sizes, int n_in,
                              void* d_out, int out_size)
{
    (void)in_sizes; (void)n_in; (void)out_size;
    const float* x    = (const float*)d_in[0];
    const float* c1c  = (const float*)d_in[1];
    const float* c1l  = (const float*)d_in[2];
    const float* c1t  = (const float*)d_in[3];
    const float* c2c  = (const float*)d_in[4];
    const float* c2l  = (const float*)d_in[5];
    const float* c2t  = (const float*)d_in[6];
    const float* c3c  = (const float*)d_in[7];
    const float* c3l  = (const float*)d_in[8];
    const float* c3t  = (const float*)d_in[9];
    const float* bn1g = (const float*)d_in[10];
    const float* bn1b = (const float*)d_in[11];
    const float* bn2g = (const float*)d_in[12];
    const float* bn2b = (const float*)d_in[13];
    const float* bn3g = (const float*)d_in[14];
    const float* bn3b = (const float*)d_in[15];
    float* out = (float*)d_out;

    amm1_kernel<<<NPOS / TILE_N, 256>>>(x, c1c, c1l, c1t);
    bn_stats_kernel<<<WIDTH, 256>>>(0, bn1g, bn1b);
    amm2_kernel<<<NPOS / TILE_N, 256>>>(c2c, c2l, c2t);
    bn_stats_kernel<<<WIDTH, 256>>>(1, bn2g, bn2b);
    amm3_kernel<<<dim3(NPOS / TILE_N, 4), 256>>>(c3c, c3l, c3t);
    bn_stats_kernel<<<OUTC, 256>>>(2, bn3g, bn3b);
    final_kernel<<<(B_ * OUTC * L_ + 255) / 256, 256>>>(x, out);
}

// round 12
// speedup vs baseline: 1.7633x; 1.0785x over previous
#include <cuda_runtime.h>
#include <cstdint>

#define B_    32
#define H_    14
#define W_    14
#define L_    196
#define NPOS  6272
#define CIN   1024
#define WIDTH 256
#define OUTC  1024
#define SAF   20          // attn row stride (floats)
#define NBLK  296         // 2 * 148 SMs exactly
#define TBASE 21          // 296*21 = 6216, remainder 56 -> first 56 blocks get 22

// ---------------- static scratch ----------------
__device__ float g_out1[WIDTH * NPOS];   // channel-major [c][n]
__device__ float g_out2[WIDTH * NPOS];
__device__ float g_out3[OUTC  * NPOS];
__device__ float g_sc1[WIDTH], g_sh1[WIDTH];
__device__ float g_sc2[WIDTH], g_sh2[WIDTH];
__device__ float g_sc3[OUTC],  g_sh3[OUTC];

// ---------------- helpers ----------------
__device__ __forceinline__ float red_max16(float v) {
#pragma unroll
    for (int d = 8; d; d >>= 1) v = fmaxf(v, __shfl_xor_sync(0xffffffffu, v, d, 16));
    return v;
}
__device__ __forceinline__ float red_sum16(float v) {
#pragma unroll
    for (int d = 8; d; d >>= 1) v += __shfl_xor_sync(0xffffffffu, v, d, 16);
    return v;
}

// 24x16x256 GEMM slice per block-iteration; warp-uniform pn, po in [0,64)
__device__ __forceinline__ void gemm_cb(const float* attn, const float4* lut4,
                                        int pn, int po, float acc[6][4]) {
#pragma unroll
    for (int kb = 0; kb < 4; ++kb) {
        const float4 bv0 = lut4[(kb * 4 + 0) * 64 + po];
        const float4 bv1 = lut4[(kb * 4 + 1) * 64 + po];
        const float4 bv2 = lut4[(kb * 4 + 2) * 64 + po];
        const float4 bv3 = lut4[(kb * 4 + 3) * 64 + po];
#pragma unroll
        for (int i = 0; i < 6; ++i) {
            const float4 a = *(const float4*)(attn + (pn * 6 + i) * SAF + kb * 4);
            acc[i][0] = fmaf(a.x, bv0.x, acc[i][0]);
            acc[i][1] = fmaf(a.x, bv0.y, acc[i][1]);
            acc[i][2] = fmaf(a.x, bv0.z, acc[i][2]);
            acc[i][3] = fmaf(a.x, bv0.w, acc[i][3]);
            acc[i][0] = fmaf(a.y, bv1.x, acc[i][0]);
            acc[i][1] = fmaf(a.y, bv1.y, acc[i][1]);
            acc[i][2] = fmaf(a.y, bv1.z, acc[i][2]);
            acc[i][3] = fmaf(a.y, bv1.w, acc[i][3]);
            acc[i][0] = fmaf(a.z, bv2.x, acc[i][0]);
            acc[i][1] = fmaf(a.z, bv2.y, acc[i][1]);
            acc[i][2] = fmaf(a.z, bv2.z, acc[i][2]);
            acc[i][3] = fmaf(a.z, bv2.w, acc[i][3]);
            acc[i][0] = fmaf(a.w, bv3.x, acc[i][0]);
            acc[i][1] = fmaf(a.w, bv3.y, acc[i][1]);
            acc[i][2] = fmaf(a.w, bv3.z, acc[i][2]);
            acc[i][3] = fmaf(a.w, bv3.w, acc[i][3]);
        }
    }
}

__device__ __forceinline__ void epi_store(float* dst, int obase, int n0, int TILE,
                                          int pn, int po, const float acc[6][4]) {
#pragma unroll
    for (int i = 0; i < 6; ++i) {
        const int row = pn * 6 + i;
        if (row < TILE) {
            const int n = n0 + row;
#pragma unroll
            for (int q = 0; q < 4; ++q)
                dst[(size_t)(obase + po * 4 + q) * NPOS + n] = acc[i][q];
        }
    }
}

// ======================= AMM layer 1 (1x1, ncb=256, sub=4) =================
__global__ __launch_bounds__(256, 2) void amm1_kernel(
    const float* __restrict__ x, const float* __restrict__ cent,
    const float* __restrict__ lut, const float* __restrict__ invt_p)
{
    __shared__ float lut_s[16 * 256];      // 16 KB
    __shared__ float attn_s[24 * SAF];

    const int t = threadIdx.x, bx = blockIdx.x;
    const int TILE = TBASE + (bx < 56);
    const int n0 = bx * TBASE + (bx < 56 ? bx : 56);
    const float invt = __ldg(invt_p);
    const int po = t & 63, pn = t >> 6, gg = t >> 4, kk = t & 15;

    float acc[6][4];
#pragma unroll
    for (int i = 0; i < 6; ++i)
#pragma unroll
        for (int q = 0; q < 4; ++q) acc[i][q] = 0.f;

    // per-pass scoring geometry (fixed)
    bool pV[2]; int pB[2], pL[2];
#pragma unroll
    for (int ps = 0; ps < 2; ++ps) {
        const int pp = ps * 16 + gg;
        pV[ps] = pp < TILE;
        const int n = n0 + (pV[ps] ? pp : 0);
        pB[ps] = n / L_;
        pL[ps] = n - pB[ps] * L_;
    }

    float4 lr[4];
    float xv[2][4], cw[4];

#define L1_LOAD(c)                                                              \
    do {                                                                        \
        _Pragma("unroll")                                                       \
        for (int r = 0; r < 4; ++r) {                                           \
            const int j = t + r * 256, k = j >> 6, o4 = j & 63;                 \
            lr[r] = __ldg((const float4*)(lut + ((size_t)(c) * 16 + k) * 256) + o4); \
        }                                                                       \
        const float* cp = cent + ((size_t)(c) * 16 + kk) * 4;                   \
        cw[0] = __ldg(cp); cw[1] = __ldg(cp + 1);                               \
        cw[2] = __ldg(cp + 2); cw[3] = __ldg(cp + 3);                           \
        _Pragma("unroll")                                                       \
        for (int ps = 0; ps < 2; ++ps) {                                        \
            const float* xp = x + ((size_t)pB[ps] * CIN + (c) * 4) * L_ + pL[ps]; \
            xv[ps][0] = __ldg(xp);          xv[ps][1] = __ldg(xp + L_);         \
            xv[ps][2] = __ldg(xp + 2 * L_); xv[ps][3] = __ldg(xp + 3 * L_);     \
        }                                                                       \
    } while (0)

#define L1_COMMIT()                                                             \
    do {                                                                        \
        const float nrm = cw[0]*cw[0] + cw[1]*cw[1] + cw[2]*cw[2] + cw[3]*cw[3];\
        _Pragma("unroll")                                                       \
        for (int ps = 0; ps < 2; ++ps) {                                        \
            float s = -1e30f;                                                   \
            if (pV[ps]) {                                                       \
                const float d = cw[0]*xv[ps][0] + cw[1]*xv[ps][1]               \
                              + cw[2]*xv[ps][2] + cw[3]*xv[ps][3];              \
                s = (2.f * d - nrm) * invt;                                     \
            }                                                                   \
            const float m = red_max16(s);                                       \
            const float e = pV[ps] ? __expf(s - m) : 0.f;                       \
            const float sum = red_sum16(e);                                     \
            if (pV[ps]) attn_s[(ps * 16 + gg) * SAF + kk] = e / sum;            \
        }                                                                       \
        _Pragma("unroll")                                                       \
        for (int r = 0; r < 4; ++r) ((float4*)lut_s)[t + r * 256] = lr[r];      \
    } while (0)

    L1_LOAD(0); L1_COMMIT(); __syncthreads();
    for (int c = 0; c < 256; ++c) {
        if (c + 1 < 256) L1_LOAD(c + 1);
        gemm_cb(attn_s, (const float4*)lut_s, pn, po, acc);
        __syncthreads();
        if (c + 1 < 256) L1_COMMIT();
        __syncthreads();
    }
    epi_store(g_out1, 0, n0, TILE, pn, po, acc);
}

// ============ AMM layer 2 (3x3 patches, ncb=256, sub=9, bn1+relu fused) ====
__global__ __launch_bounds__(256, 2) void amm2_kernel(
    const float* __restrict__ cent, const float* __restrict__ lut,
    const float* __restrict__ invt_p)
{
    __shared__ float lut_s[16 * 256];
    __shared__ float attn_s[24 * SAF];

    const int t = threadIdx.x, bx = blockIdx.x;
    const int TILE = TBASE + (bx < 56);
    const int n0 = bx * TBASE + (bx < 56 ? bx : 56);
    const float invt = __ldg(invt_p);
    const int po = t & 63, pn = t >> 6, gg = t >> 4, kk = t & 15;

    float acc[6][4];
#pragma unroll
    for (int i = 0; i < 6; ++i)
#pragma unroll
        for (int q = 0; q < 4; ++q) acc[i][q] = 0.f;

    // fixed per-pass 3x3 gather geometry
    bool pV[2]; int posn[2][9]; unsigned vmask[2];
#pragma unroll
    for (int ps = 0; ps < 2; ++ps) {
        const int pp = ps * 16 + gg;
        pV[ps] = pp < TILE;
        const int n = n0 + (pV[ps] ? pp : 0);
        const int b = n / L_, l = n - (n / L_) * L_;
        const int h = l / W_, w = l - (l / W_) * W_;
        vmask[ps] = 0;
#pragma unroll
        for (int j = 0; j < 9; ++j) {
            const int hh = h + j / 3 - 1, ww = w + j % 3 - 1;
            const bool v = (hh >= 0 && hh < H_ && ww >= 0 && ww < W_);
            if (v) vmask[ps] |= 1u << j;
            posn[ps][j] = b * L_ + (v ? hh * W_ + ww : 0);
        }
    }

    float4 lr[4];
    float xv[2][9], cw[9], sc1v, sh1v;

#define L2_LOAD(c)                                                              \
    do {                                                                        \
        _Pragma("unroll")                                                       \
        for (int r = 0; r < 4; ++r) {                                           \
            const int j = t + r * 256, k = j >> 6, o4 = j & 63;                 \
            lr[r] = __ldg((const float4*)(lut + ((size_t)(c) * 16 + k) * 256) + o4); \
        }                                                                       \
        const float* cp = cent + ((size_t)(c) * 16 + kk) * 9;                   \
        _Pragma("unroll")                                                       \
        for (int j = 0; j < 9; ++j) cw[j] = __ldg(cp + j);                      \
        sc1v = g_sc1[c]; sh1v = g_sh1[c];                                       \
        _Pragma("unroll")                                                       \
        for (int ps = 0; ps < 2; ++ps)                                          \
            _Pragma("unroll")                                                   \
            for (int j = 0; j < 9; ++j)                                         \
                xv[ps][j] = __ldg(g_out1 + (size_t)(c) * NPOS + posn[ps][j]);   \
    } while (0)

#define L2_COMMIT()                                                             \
    do {                                                                        \
        float nrm = 0.f;                                                        \
        _Pragma("unroll")                                                       \
        for (int j = 0; j < 9; ++j) nrm = fmaf(cw[j], cw[j], nrm);              \
        _Pragma("unroll")                                                       \
        for (int ps = 0; ps < 2; ++ps) {                                        \
            float s = -1e30f;                                                   \
            if (pV[ps]) {                                                       \
                float d = 0.f;                                                  \
                _Pragma("unroll")                                               \
                for (int j = 0; j < 9; ++j) {                                   \
                    const float v = (vmask[ps] >> j) & 1u                       \
                        ? fmaxf(fmaf(xv[ps][j], sc1v, sh1v), 0.f) : 0.f;        \
                    d = fmaf(cw[j], v, d);                                      \
                }                                                               \
                s = (2.f * d - nrm) * invt;                                     \
            }                                                                   \
            const float m = red_max16(s);                                       \
            const float e = pV[ps] ? __expf(s - m) : 0.f;                       \
            const float sum = red_sum16(e);                                     \
            if (pV[ps]) attn_s[(ps * 16 + gg) * SAF + kk] = e / sum;            \
        }                                                                       \
        _Pragma("unroll")                                                       \
        for (int r = 0; r < 4; ++r) ((float4*)lut_s)[t + r * 256] = lr[r];      \
    } while (0)

    L2_LOAD(0); L2_COMMIT(); __syncthreads();
    for (int c = 0; c < 256; ++c) {
        if (c + 1 < 256) L2_LOAD(c + 1);
        gemm_cb(attn_s, (const float4*)lut_s, pn, po, acc);
        __syncthreads();
        if (c + 1 < 256) L2_COMMIT();
        __syncthreads();
    }
    epi_store(g_out2, 0, n0, TILE, pn, po, acc);
}

// ======= AMM layer 3 (1x1, ncb=64, sub=4, out=1024, bn2+relu fused) ========
__global__ __launch_bounds__(256, 2) void amm3_kernel(
    const float* __restrict__ cent, const float* __restrict__ lut,
    const float* __restrict__ invt_p)
{
    __shared__ float lut_s[16 * 256];
    __shared__ float attn_s[24 * SAF];

    const int t = threadIdx.x, bx = blockIdx.x;
    const int chunk = blockIdx.y;
    const int TILE = TBASE + (bx < 56);
    const int n0 = bx * TBASE + (bx < 56 ? bx : 56);
    const float invt = __ldg(invt_p);
    const int po = t & 63, pn = t >> 6, gg = t >> 4, kk = t & 15;

    float acc[6][4];
#pragma unroll
    for (int i = 0; i < 6; ++i)
#pragma unroll
        for (int q = 0; q < 4; ++q) acc[i][q] = 0.f;

    bool pV[2]; int pN[2];
#pragma unroll
    for (int ps = 0; ps < 2; ++ps) {
        const int pp = ps * 16 + gg;
        pV[ps] = pp < TILE;
        pN[ps] = n0 + (pV[ps] ? pp : 0);
    }

    float4 lr[4];
    float xv[2][4], cw[4], scv[4], shv[4];

#define L3_LOAD(c)                                                              \
    do {                                                                        \
        _Pragma("unroll")                                                       \
        for (int r = 0; r < 4; ++r) {                                           \
            const int j = t + r * 256, k = j >> 6, o4 = j & 63;                 \
            lr[r] = __ldg((const float4*)(lut + ((size_t)(c) * 16 + k) * 1024   \
                                           + chunk * 256) + o4);                \
        }                                                                       \
        const float* cp = cent + ((size_t)(c) * 16 + kk) * 4;                   \
        cw[0] = __ldg(cp); cw[1] = __ldg(cp + 1);                               \
        cw[2] = __ldg(cp + 2); cw[3] = __ldg(cp + 3);                           \
        const int ch0 = (c) * 4;                                                \
        _Pragma("unroll")                                                       \
        for (int j = 0; j < 4; ++j) { scv[j] = g_sc2[ch0 + j]; shv[j] = g_sh2[ch0 + j]; } \
        _Pragma("unroll")                                                       \
        for (int ps = 0; ps < 2; ++ps)                                          \
            _Pragma("unroll")                                                   \
            for (int j = 0; j < 4; ++j)                                         \
                xv[ps][j] = __ldg(g_out2 + (size_t)(ch0 + j) * NPOS + pN[ps]);  \
    } while (0)

#define L3_COMMIT()                                                             \
    do {                                                                        \
        const float nrm = cw[0]*cw[0] + cw[1]*cw[1] + cw[2]*cw[2] + cw[3]*cw[3];\
        _Pragma("unroll")                                                       \
        for (int ps = 0; ps < 2; ++ps) {                                        \
            float s = -1e30f;                                                   \
            if (pV[ps]) {                                                       \
                float d = 0.f;                                                  \
                _Pragma("unroll")                                               \
                for (int j = 0; j < 4; ++j) {                                   \
                    const float v = fmaxf(fmaf(xv[ps][j], scv[j], shv[j]), 0.f);\
                    d = fmaf(cw[j], v, d);                                      \
                }                                                               \
                s = (2.f * d - nrm) * invt;                                     \
            }                                                                   \
            const float m = red_max16(s);                                       \
            const float e = pV[ps] ? __expf(s - m) : 0.f;                       \
            const float sum = red_sum16(e);                                     \
            if (pV[ps]) attn_s[(ps * 16 + gg) * SAF + kk] = e / sum;            \
        }                                                                       \
        _Pragma("unroll")                                                       \
        for (int r = 0; r < 4; ++r) ((float4*)lut_s)[t + r * 256] = lr[r];      \
    } while (0)

    L3_LOAD(0); L3_COMMIT(); __syncthreads();
    for (int c = 0; c < 64; ++c) {
        if (c + 1 < 64) L3_LOAD(c + 1);
        gemm_cb(attn_s, (const float4*)lut_s, pn, po, acc);
        __syncthreads();
        if (c + 1 < 64) L3_COMMIT();
        __syncthreads();
    }
    epi_store(g_out3, chunk * 256, n0, TILE, pn, po, acc);
}

// ================== BN batch-stats (one block per channel) =================
__global__ __launch_bounds__(256) void bn_stats_kernel(
    int which, const float* __restrict__ gw, const float* __restrict__ bw)
{
    const float* data; float* scale; float* shift;
    if (which == 0)      { data = g_out1; scale = g_sc1; shift = g_sh1; }
    else if (which == 1) { data = g_out2; scale = g_sc2; shift = g_sh2; }
    else                 { data = g_out3; scale = g_sc3; shift = g_sh3; }

    const int c = blockIdx.x, t = threadIdx.x;
    const float* p = data + (size_t)c * NPOS;
    float s = 0.f, s2 = 0.f;
    for (int i = t; i < NPOS; i += 256) {
        const float v = p[i];
        s += v; s2 += v * v;
    }
#pragma unroll
    for (int d = 16; d; d >>= 1) {
        s  += __shfl_xor_sync(0xffffffffu, s,  d);
        s2 += __shfl_xor_sync(0xffffffffu, s2, d);
    }
    __shared__ float sh_s[8], sh_s2[8];
    if ((t & 31) == 0) { sh_s[t >> 5] = s; sh_s2[t >> 5] = s2; }
    __syncthreads();
    if (t == 0) {
        s = 0.f; s2 = 0.f;
#pragma unroll
        for (int i = 0; i < 8; ++i) { s += sh_s[i]; s2 += sh_s2[i]; }
        const float m   = s  * (1.f / NPOS);
        const float var = s2 * (1.f / NPOS) - m * m;
        const float sc  = __ldg(gw + c) * rsqrtf(var + 1e-5f);
        scale[c] = sc;
        shift[c] = __ldg(bw + c) - m * sc;
    }
}

// ============== final: bn3 + residual + relu ===============================
__global__ __launch_bounds__(256) void final_kernel(
    const float* __restrict__ x, float* __restrict__ out)
{
    const int idx = blockIdx.x * 256 + threadIdx.x;
    if (idx >= B_ * OUTC * L_) return;
    const int l = idx % L_;
    const int c = (idx / L_) % OUTC;
    const int b = idx / (L_ * OUTC);
    const int n = b * L_ + l;
    const float v = g_out3[(size_t)c * NPOS + n] * g_sc3[c] + g_sh3[c] + x[idx];
    out[idx] = fmaxf(v, 0.f);
}

// ==========================================================================
extern "C" void kernel_launch(void* const* d_in, const int* in_sizes, int n_in,
                              void* d_out, int out_size)
{
    (void)in_sizes; (void)n_in; (void)out_size;
    const float* x    = (const float*)d_in[0];
    const float* c1c  = (const float*)d_in[1];
    const float* c1l  = (const float*)d_in[2];
    const float* c1t  = (const float*)d_in[3];
    const float* c2c  = (const float*)d_in[4];
    const float* c2l  = (const float*)d_in[5];
    const float* c2t  = (const float*)d_in[6];
    const float* c3c  = (const float*)d_in[7];
    const float* c3l  = (const float*)d_in[8];
    const float* c3t  = (const float*)d_in[9];
    const float* bn1g = (const float*)d_in[10];
    const float* bn1b = (const float*)d_in[11];
    const float* bn2g = (const float*)d_in[12];
    const float* bn2b = (const float*)d_in[13];
    const float* bn3g = (const float*)d_in[14];
    const float* bn3b = (const float*)d_in[15];
    float* out = (float*)d_out;

    amm1_kernel<<<NBLK, 256>>>(x, c1c, c1l, c1t);
    bn_stats_kernel<<<WIDTH, 256>>>(0, bn1g, bn1b);

    amm2_kernel<<<NBLK, 256>>>(c2c, c2l, c2t);
    bn_stats_kernel<<<WIDTH, 256>>>(1, bn2g, bn2b);

    amm3_kernel<<<dim3(NBLK, 4), 256>>>(c3c, c3l, c3t);
    bn_stats_kernel<<<OUTC, 256>>>(2, bn3g, bn3b);
    final_kernel<<<(B_ * OUTC * L_ + 255) / 256, 256>>>(x, out);
}